// round 15
// baseline (speedup 1.0000x reference)
#include <cuda_runtime.h>
#include <cuda_fp16.h>
#include <cstdint>

#define NPTS 16384
#define HID  256
#define NUF  0.01f
static constexpr size_t NEL = (size_t)NPTS * HID;
static constexpr int NCH = 5;                       // h, h_t, h_x, h_y, h_L (Laplacian)
static constexpr int MT = 80;                       // 16 points x 5 channels
static constexpr int GRID_M = NCH * NPTS / MT;      // 1024
static constexpr int NTHR = 256;
static constexpr float DSC  = 0.0625f;
static constexpr float DSCI = 16.0f;

// stage layout (bytes): A hi/lo 80x64 f16, W hi/lo 256x64 f16
static constexpr int ST_AH = 0;
static constexpr int ST_AL = 10240;
static constexpr int ST_WH = 20480;
static constexpr int ST_WL = 53248;
static constexpr int STAGE = 86016;
static constexpr int SMEM_BYTES = 2 * STAGE;        // 172032
static constexpr int ZS_LD = 264;                   // fp32 stride of epilogue staging (80 x 264)

__device__ __align__(256) __half g_sh[NCH * NEL];   // state hi (rho layout)
__device__ __align__(256) __half g_sl[NCH * NEL];   // state lo
__device__ __align__(256) __half g_wh[5][65536];    // W^T hi [n][k]
__device__ __align__(256) __half g_wl[5][65536];    // W^T lo

__device__ __forceinline__ uint32_t smem_u32(const void* p) {
    uint32_t a;
    asm("{ .reg .u64 t; cvta.to.shared.u64 t, %1; cvt.u32.u64 %0, t; }" : "=r"(a) : "l"(p));
    return a;
}
__device__ __forceinline__ uint32_t swz(uint32_t o) { return o ^ ((o >> 3) & 0x70); }
__device__ __forceinline__ void cp16(uint32_t dst, const void* src) {
    asm volatile("cp.async.cg.shared.global [%0], [%1], 16;" :: "r"(dst), "l"(src) : "memory");
}
__device__ __forceinline__ void ldsm4(uint32_t* r, uint32_t addr) {
    asm volatile("ldmatrix.sync.aligned.m8n8.x4.shared.b16 {%0,%1,%2,%3}, [%4];"
                 : "=r"(r[0]), "=r"(r[1]), "=r"(r[2]), "=r"(r[3]) : "r"(addr));
}
__device__ __forceinline__ void mma16816(float* c, const uint32_t* a, uint32_t b0, uint32_t b1) {
    asm volatile("mma.sync.aligned.m16n8k16.row.col.f32.f16.f16.f32 "
                 "{%0,%1,%2,%3}, {%4,%5,%6,%7}, {%8,%9}, {%0,%1,%2,%3};"
                 : "+f"(c[0]), "+f"(c[1]), "+f"(c[2]), "+f"(c[3])
                 : "r"(a[0]), "r"(a[1]), "r"(a[2]), "r"(a[3]), "r"(b0), "r"(b1));
}
__device__ __forceinline__ void split16(float x, __half& h, __half& l) {
    h = __float2half_rn(x);
    l = __float2half_rn(x - __half2float(h));
}
// rho-layout row index for (point p, channel ch)
__device__ __forceinline__ size_t rho(int p, int ch) {
    return (size_t)(p >> 4) * MT + ch * 16 + (p & 15);
}

// ---------- compile-time-sized per-chunk compute: no barriers inside ----------
template <int MIW, int WARPM>
__device__ __forceinline__ void chunk_compute(uint32_t base, int warpN, int roff, int koff,
                                              float (&acc)[3][8][4]) {
#pragma unroll
    for (int ks = 0; ks < 4; ks++) {
        const int kb = ks * 32 + koff;
        uint32_t a_hi[MIW][4], a_lo[MIW][4], bq[4][4];
#pragma unroll
        for (int p = 0; p < 4; p++)
            ldsm4(bq[p], base + ST_WH + swz((warpN + p * 16 + roff) * 128 + kb));
#pragma unroll
        for (int mi = 0; mi < MIW; mi++)
            ldsm4(a_hi[mi], base + ST_AH + swz((WARPM + mi * 16 + roff) * 128 + kb));
        // main: hi*hi
#pragma unroll
        for (int mi = 0; mi < MIW; mi++)
#pragma unroll
            for (int p = 0; p < 4; p++) {
                mma16816(acc[mi][2 * p],     a_hi[mi], bq[p][0], bq[p][2]);
                mma16816(acc[mi][2 * p + 1], a_hi[mi], bq[p][1], bq[p][3]);
            }
        // lo*hi
#pragma unroll
        for (int mi = 0; mi < MIW; mi++)
            ldsm4(a_lo[mi], base + ST_AL + swz((WARPM + mi * 16 + roff) * 128 + kb));
#pragma unroll
        for (int mi = 0; mi < MIW; mi++)
#pragma unroll
            for (int p = 0; p < 4; p++) {
                mma16816(acc[mi][2 * p],     a_lo[mi], bq[p][0], bq[p][2]);
                mma16816(acc[mi][2 * p + 1], a_lo[mi], bq[p][1], bq[p][3]);
            }
        // hi*lo
#pragma unroll
        for (int p = 0; p < 4; p++)
            ldsm4(bq[p], base + ST_WL + swz((warpN + p * 16 + roff) * 128 + kb));
#pragma unroll
        for (int mi = 0; mi < MIW; mi++)
#pragma unroll
            for (int p = 0; p < 4; p++) {
                mma16816(acc[mi][2 * p],     a_hi[mi], bq[p][0], bq[p][2]);
                mma16816(acc[mi][2 * p + 1], a_hi[mi], bq[p][1], bq[p][3]);
            }
    }
}

template <int MIW, int WARPM>
__device__ __forceinline__ void stage_store(float* Zs, int warpN, int qr, int qc,
                                            float (&acc)[3][8][4]) {
#pragma unroll
    for (int mi = 0; mi < MIW; mi++) {
        const int r0 = WARPM + mi * 16 + qr;
#pragma unroll
        for (int nj = 0; nj < 8; nj++) {
            const int col = warpN + nj * 8 + qc;
            *(float2*)(Zs + (size_t)r0 * ZS_LD + col) =
                make_float2(acc[mi][nj][0], acc[mi][nj][1]);
            *(float2*)(Zs + (size_t)(r0 + 8) * ZS_LD + col) =
                make_float2(acc[mi][nj][2], acc[mi][nj][3]);
        }
    }
}

// ---------- weight prep: W^T split into fp16 hi/lo ----------
__global__ void k_wprep(const float* W1, const float* W2, const float* W3,
                        const float* W4, const float* W5,
                        __half* __restrict__ wh, __half* __restrict__ wl) {
    int L = blockIdx.y, k = blockIdx.x, n = threadIdx.x;
    const float* W = (L == 0) ? W1 : (L == 1) ? W2 : (L == 2) ? W3 : (L == 3) ? W4 : W5;
    float w = W[k * 256 + n];
    __half h, l;
    split16(w, h, l);
    size_t o = (size_t)L * 65536 + (size_t)n * 256 + k;
    wh[o] = h;
    wl[o] = l;
}

// ---------- layer 0: inputs -> activated 5-channel state, rho layout ----------
__global__ void k_init(const float* __restrict__ t, const float* __restrict__ x,
                       const float* __restrict__ y, const float* __restrict__ W0,
                       const float* __restrict__ b0,
                       __half* __restrict__ oh, __half* __restrict__ ol) {
    int i = blockIdx.x, j = threadIdx.x;
    float w0 = W0[j], w1 = W0[256 + j], w2 = W0[512 + j];
    float a = t[i] * w0 + x[i] * w1 + y[i] * w2 + b0[j];
    float s, c;
    sincosf(a, &s, &c);
    float r[NCH] = {s, c * w0, c * w1, c * w2, -s * (w1 * w1 + w2 * w2)};
#pragma unroll
    for (int ch = 0; ch < NCH; ch++) {
        float v = (ch == 0) ? r[ch] : r[ch] * DSC;
        __half h, l;
        split16(v, h, l);
        size_t o = rho(i, ch) * 256 + j;
        oh[o] = h;
        ol[o] = l;
    }
}

// ---------- fused fp16x3 GEMM + activation, in place ----------
__global__ void __launch_bounds__(NTHR, 1)
k_gemm(__half* __restrict__ Sh, __half* __restrict__ Sl,
       const __half* __restrict__ Wh, const __half* __restrict__ Wl,
       const float* __restrict__ b) {
    extern __shared__ char smem[];
    const uint32_t sb = smem_u32(smem);
    const int tid = threadIdx.x, lane = tid & 31, wid = tid >> 5;
    const int mt = blockIdx.x;
    // warps 0-3: rows 0-47 (3 mi-tiles); warps 4-7: rows 48-79 (2 mi-tiles). One of each per SMSP.
    const int hiW  = wid >> 2;
    const int warpN = (wid & 3) * 64;

    const __half* arh = Sh + (size_t)mt * MT * 256;
    const __half* arl = Sl + (size_t)mt * MT * 256;

    auto issue = [&](int c, int buf) {
        uint32_t base = sb + buf * STAGE;
        // A hi/lo: 80 rows x 8 groups x2 = 1280 blocks, 5 iters
#pragma unroll
        for (int i = 0; i < 5; i++) {
            int idx = tid + i * NTHR;
            int m = idx >= 640;
            int rr = idx - (m ? 640 : 0);
            int r = rr >> 3, q = rr & 7;
            const __half* src = m ? arl : arh;
            cp16(base + (m ? ST_AL : ST_AH) + swz(r * 128 + q * 16),
                 src + (size_t)r * 256 + c * 64 + q * 8);
        }
        // W hi/lo: 256 rows x 8 groups x2 = 4096 blocks, 16 iters
#pragma unroll
        for (int i = 0; i < 16; i++) {
            int idx = tid + i * NTHR;
            int m = idx >= 2048;
            int rr = idx & 2047;
            int n = rr >> 3, q = rr & 7;
            const __half* src = m ? Wl : Wh;
            cp16(base + (m ? ST_WL : ST_WH) + swz(n * 128 + q * 16),
                 src + (size_t)n * 256 + c * 64 + q * 8);
        }
        asm volatile("cp.async.commit_group;" ::: "memory");
    };

    float acc[3][8][4];
#pragma unroll
    for (int mi = 0; mi < 3; mi++)
        for (int nj = 0; nj < 8; nj++)
            for (int q = 0; q < 4; q++) acc[mi][nj][q] = 0.f;

    issue(0, 0);
    issue(1, 1);

    const int lr = lane & 7, g = lane >> 3;
    const int roff = (g & 1) * 8 + lr;
    const int koff = (g >> 1) * 16;

    for (int c = 0; c < 4; c++) {
        const int buf = c & 1;
        if (c < 3) asm volatile("cp.async.wait_group 1;" ::: "memory");
        else       asm volatile("cp.async.wait_group 0;" ::: "memory");
        __syncthreads();
        const uint32_t base = sb + buf * STAGE;

        // compile-time instruction streams per warp class; no barriers inside
        if (hiW == 0) chunk_compute<3, 0>(base, warpN, roff, koff, acc);
        else          chunk_compute<2, 48>(base, warpN, roff, koff, acc);

        __syncthreads();
        if (c + 2 < 4) issue(c + 2, buf);
    }

    // ---- fused epilogue: stage Z, apply bias + sin chain rule (5-ch), store in place ----
    float* Zs = (float*)smem;                         // 80 x ZS_LD fp32 = 84480 B
    const int qr = lane >> 2, qc = (lane & 3) * 2;
    if (hiW == 0) stage_store<3, 0>(Zs, warpN, qr, qc, acc);
    else          stage_store<2, 48>(Zs, warpN, qr, qc, acc);
    __syncthreads();

    const int j = tid;
    const float bj = __ldg(b + j);
    const size_t g0 = (size_t)mt * MT;
#pragma unroll 4
    for (int pl = 0; pl < 16; pl++) {
        float a0 = Zs[(0 * 16 + pl) * ZS_LD + j] + bj;
        float a1 = Zs[(1 * 16 + pl) * ZS_LD + j] * DSCI;   // t
        float a2 = Zs[(2 * 16 + pl) * ZS_LD + j] * DSCI;   // x
        float a3 = Zs[(3 * 16 + pl) * ZS_LD + j] * DSCI;   // y
        float a4 = Zs[(4 * 16 + pl) * ZS_LD + j] * DSCI;   // Laplacian
        float s, c;
        sincosf(a0, &s, &c);
        float r[NCH] = {s, c * a1, c * a2, c * a3,
                        c * a4 - s * (a2 * a2 + a3 * a3)};
#pragma unroll
        for (int ch = 0; ch < NCH; ch++) {
            float v = (ch == 0) ? r[ch] : r[ch] * DSC;
            __half h, l;
            split16(v, h, l);
            size_t o = (g0 + ch * 16 + pl) * 256 + j;
            Sh[o] = h;
            Sl[o] = l;
        }
    }
}

// ---------- final layer (256->3) + NS residuals, 5-channel ----------
__global__ void k_final(const __half* __restrict__ ih, const __half* __restrict__ il,
                        const float* __restrict__ W6, const float* __restrict__ b6,
                        float* __restrict__ out) {
    const int warp = (blockIdx.x * blockDim.x + threadIdx.x) >> 5;
    const int lane = threadIdx.x & 31;
    if (warp >= NPTS) return;
    float acc[NCH][3];
#pragma unroll
    for (int ch = 0; ch < NCH; ch++)
        for (int o = 0; o < 3; o++) acc[ch][o] = 0.f;
    for (int k = lane; k < HID; k += 32) {
        float w0 = W6[k * 3], w1 = W6[k * 3 + 1], w2 = W6[k * 3 + 2];
#pragma unroll
        for (int ch = 0; ch < NCH; ch++) {
            size_t o = rho(warp, ch) * 256 + k;
            float h = __half2float(ih[o]) + __half2float(il[o]);
            acc[ch][0] += h * w0; acc[ch][1] += h * w1; acc[ch][2] += h * w2;
        }
    }
#pragma unroll
    for (int ch = 0; ch < NCH; ch++)
        for (int o = 0; o < 3; o++)
            for (int off = 16; off; off >>= 1)
                acc[ch][o] += __shfl_xor_sync(0xFFFFFFFFu, acc[ch][o], off);
    if (lane == 0) {
        float u = acc[0][0] + b6[0], v = acc[0][1] + b6[1];
        float ut = acc[1][0] * DSCI, vt = acc[1][1] * DSCI;
        float ux = acc[2][0] * DSCI, vx = acc[2][1] * DSCI, px = acc[2][2] * DSCI;
        float uy = acc[3][0] * DSCI, vy = acc[3][1] * DSCI, py = acc[3][2] * DSCI;
        float lapU = acc[4][0] * DSCI, lapV = acc[4][1] * DSCI;
        out[0 * NPTS + warp] = ut + (u * ux + v * uy) + px - NUF * lapU;
        out[1 * NPTS + warp] = vt + (u * vx + v * vy) + py - NUF * lapV;
        out[2 * NPTS + warp] = ux + vy;
    }
}

extern "C" void kernel_launch(void* const* d_in, const int* in_sizes, int n_in,
                              void* d_out, int out_size) {
    const float* t  = (const float*)d_in[0];
    const float* x  = (const float*)d_in[1];
    const float* y  = (const float*)d_in[2];
    const float* W0 = (const float*)d_in[3];
    const float* b0 = (const float*)d_in[4];
    const float* Wm[5] = {(const float*)d_in[5], (const float*)d_in[7], (const float*)d_in[9],
                          (const float*)d_in[11], (const float*)d_in[13]};
    const float* bm[5] = {(const float*)d_in[6], (const float*)d_in[8], (const float*)d_in[10],
                          (const float*)d_in[12], (const float*)d_in[14]};
    const float* W6 = (const float*)d_in[15];
    const float* b6 = (const float*)d_in[16];
    float* out = (float*)d_out;

    __half *sh, *sl, *wh, *wl;
    cudaGetSymbolAddress((void**)&sh, g_sh);
    cudaGetSymbolAddress((void**)&sl, g_sl);
    cudaGetSymbolAddress((void**)&wh, g_wh);
    cudaGetSymbolAddress((void**)&wl, g_wl);
    cudaFuncSetAttribute(k_gemm, cudaFuncAttributeMaxDynamicSharedMemorySize, SMEM_BYTES);

    k_wprep<<<dim3(256, 5), 256>>>(Wm[0], Wm[1], Wm[2], Wm[3], Wm[4], wh, wl);
    k_init<<<NPTS, 256>>>(t, x, y, W0, b0, sh, sl);
    for (int L = 0; L < 5; L++) {
        k_gemm<<<GRID_M, NTHR, SMEM_BYTES>>>(sh, sl, wh + (size_t)L * 65536,
                                             wl + (size_t)L * 65536, bm[L]);
    }
    k_final<<<NPTS / 8, 256>>>(sh, sl, W6, b6, out);
}